// round 10
// baseline (speedup 1.0000x reference)
#include <cuda_runtime.h>

// ---------------------------------------------------------------------------
// DifferentiableRenderer: Gaussian splat weighted-average render.
// out[b,c,y,x] = sum_n w_n*color_n / (sum_n w_n + 1e-8)
// w_n = opacity_n * exp(-0.5*((x-u_n)^2+(y-v_n)^2)/var_n)
//
// R10: single fused kernel. Block = (batch, 16x16 tile, gaussian slice of 8).
//   prep (raw inputs -> u,v,a,bop) + conservative tile cull + stable
//   ballot/prefix compaction + per-pixel eval, as R9. NEW: merge is done by
//   the LAST-finishing block of each tile (threadfence + atomic counter),
//   reading the 8 partials in fixed slice order (deterministic), dividing,
//   storing 3 planes, and resetting the counter for graph replay.
//   Cut at w < 2^-60: per-pixel abs error <= ~7e-7 << 1e-3 budget.
// ---------------------------------------------------------------------------

#define HH 128
#define WW 128
#define HWP (HH * WW)
#define FXC 150.0f
#define FYC 150.0f
#define CXC 64.0f
#define CYC 64.0f
#define EPSC 1e-8f

#define TILE    16
#define TX_N    (WW / TILE)          // 8
#define TY_N    (HH / TILE)          // 8
#define TILES   (TX_N * TY_N)        // 64
#define SPLIT   8                    // gaussian slices per tile
#define TPB     256                  // threads per render block (1 px each)
#define CHUNK   256                  // gaussians prepped+tested per pass
#define EMIN    (-60.0f)             // log2 weight cutoff

#define MAXB    4

// per (b, tile, split, pixel) partial sums {den, r, g, b}
__device__ float4 g_part[MAXB * TILES * SPLIT * TPB];
// per (b, tile) arrival counters (zero-init; reset by merging block)
__device__ int g_cnt[MAXB * TILES];

__device__ __forceinline__ float ex2f(float x) {
    float y;
    asm("ex2.approx.ftz.f32 %0, %1;" : "=f"(y) : "f"(x));
    return y;
}
__device__ __forceinline__ float lg2f(float x) {
    float y;
    asm("lg2.approx.ftz.f32 %0, %1;" : "=f"(y) : "f"(x));
    return y;
}

// ---------------------------------------------------------------------------
// blockIdx.x = ((b*TILES + tile)*SPLIT + s). 256 threads = one 16x16 tile.
// ---------------------------------------------------------------------------
__global__ void __launch_bounds__(TPB)
render_tiles(float* __restrict__ out,
             const float* __restrict__ pos,
             const float* __restrict__ col,
             const float* __restrict__ opac,
             const float* __restrict__ scal,
             const float* __restrict__ qv,
             const float* __restrict__ tv,
             int N) {
    __shared__ float4 sga[CHUNK];      // u, v, a, bop
    __shared__ float4 sgb[CHUNK];      // cr, cg, cb, -
    __shared__ int s_wbase[TPB / 32];
    __shared__ int s_wcnt[TPB / 32];
    __shared__ int s_total;
    __shared__ int s_arrival;

    const int tid  = threadIdx.x;
    const int bid  = blockIdx.x;
    const int s    = bid & (SPLIT - 1);
    const int tile = (bid / SPLIT) & (TILES - 1);
    const int b    = bid / (SPLIT * TILES);
    const int m    = b * TILES + tile;            // tile slot

    const int tx = tile & (TX_N - 1);
    const int ty = tile / TX_N;
    const float pxf = (float)(tx * TILE + (tid & (TILE - 1)));
    const float pyf = (float)(ty * TILE + (tid / TILE));
    const float tcx = (float)(tx * TILE) + 7.5f;   // tile center
    const float tcy = (float)(ty * TILE) + 7.5f;

    // --- per-batch camera, hoisted (broadcast loads, L1 hits) ---
    float qw = qv[b * 4 + 0], qx = qv[b * 4 + 1];
    float qy = qv[b * 4 + 2], qz = qv[b * 4 + 3];
    {
        float inv = rsqrtf(qw * qw + qx * qx + qy * qy + qz * qz);
        qw *= inv; qx *= inv; qy *= inv; qz *= inv;
    }
    const float R00 = 1.0f - 2.0f * (qy * qy + qz * qz);
    const float R01 = 2.0f * (qx * qy - qz * qw);
    const float R02 = 2.0f * (qx * qz + qy * qw);
    const float R10 = 2.0f * (qx * qy + qz * qw);
    const float R11 = 1.0f - 2.0f * (qx * qx + qz * qz);
    const float R12 = 2.0f * (qy * qz - qx * qw);
    const float R20 = 2.0f * (qx * qz - qy * qw);
    const float R21 = 2.0f * (qy * qz + qx * qw);
    const float R22 = 1.0f - 2.0f * (qx * qx + qy * qy);
    const float t0 = tv[b * 3 + 0], t1 = tv[b * 3 + 1], t2 = tv[b * 3 + 2];

    const int lo = (s * N) / SPLIT;
    const int hi = ((s + 1) * N) / SPLIT;

    const int wid  = tid >> 5;
    const int lane = tid & 31;
    const unsigned lanemask_lt = (1u << lane) - 1u;

    float den = 0.f, ar = 0.f, ag = 0.f, ab = 0.f;

    for (int cb = lo; cb < hi; cb += CHUNK) {
        // --- prep + cull one gaussian per thread ---
        const int j = cb + tid;                    // gaussian index
        bool keep = false;
        float4 ga;
        if (j < hi) {
            const float px = pos[j * 3 + 0];
            const float py = pos[j * 3 + 1];
            const float pz = pos[j * 3 + 2];
            const float cxm = R00 * px + R01 * py + R02 * pz + t0;
            const float cym = R10 * px + R11 * py + R12 * pz + t1;
            const float czm = R20 * px + R21 * py + R22 * pz + t2;
            const float invz = __fdividef(1.0f, czm);
            const float u = cxm * invz * FXC + CXC;
            const float v = cym * invz * FYC + CYC;
            const float sc = scal[j];
            // a = -0.5 * log2(e) / var
            const float a = __fdividef(-0.72134752044448170f, sc * sc);
            const float bop = lg2f(opac[j]);       // opac=0 -> -inf -> culled
            ga = make_float4(u, v, a, bop);

            float dx = fmaxf(fabsf(u - tcx) - 7.5f, 0.0f);
            float dy = fmaxf(fabsf(v - tcy) - 7.5f, 0.0f);
            float mind2 = dx * dx + dy * dy;
            float emax  = fmaf(a, mind2, bop);     // a*mind2 + bop (a<0)
            keep = (emax >= EMIN);
        }

        // --- stable compaction (gaussian-index order preserved) ---
        const unsigned mask = __ballot_sync(0xffffffffu, keep);
        if (lane == 0) s_wcnt[wid] = __popc(mask);
        __syncthreads();
        if (tid == 0) {
            int acc = 0;
            #pragma unroll
            for (int w = 0; w < TPB / 32; w++) { s_wbase[w] = acc; acc += s_wcnt[w]; }
            s_total = acc;
        }
        __syncthreads();
        if (keep) {
            const int posn = s_wbase[wid] + __popc(mask & lanemask_lt);
            sga[posn] = ga;
            sgb[posn] = make_float4(col[j * 3 + 0], col[j * 3 + 1],
                                    col[j * 3 + 2], 0.0f);
        }
        __syncthreads();

        // --- evaluate survivors against this thread's pixel ---
        const int cnt = s_total;
        #pragma unroll 2
        for (int t = 0; t < cnt; t++) {
            const float4 A  = sga[t];              // u, v, a, bop (broadcast)
            const float4 Cc = sgb[t];
            const float dv = pyf - A.y;
            const float c2 = fmaf(A.z * dv, dv, A.w);
            const float du = pxf - A.x;
            const float e  = fmaf(A.z * du, du, c2);
            const float w  = ex2f(e);
            den += w;
            ar = fmaf(w, Cc.x, ar);
            ag = fmaf(w, Cc.y, ag);
            ab = fmaf(w, Cc.z, ab);
        }
        __syncthreads();
    }

    // --- publish this slice's partial ---
    g_part[bid * TPB + tid] = make_float4(den, ar, ag, ab);
    __threadfence();
    __syncthreads();

    // --- last-arriving block of this tile merges (deterministic order) ---
    if (tid == 0) s_arrival = atomicAdd(&g_cnt[m], 1);
    __syncthreads();

    if (s_arrival == SPLIT - 1) {
        // all 8 partials for tile m are globally visible (fence-before-atomic)
        float4 acc = make_float4(0.f, 0.f, 0.f, 0.f);
        #pragma unroll
        for (int sl = 0; sl < SPLIT; sl++) {
            const float4* p = &g_part[((m * SPLIT) + sl) * TPB + tid];
            const float4 t = __ldcg(p);            // L2 read (fresh)
            acc.x += t.x; acc.y += t.y; acc.z += t.z; acc.w += t.w;
        }
        const float invd = __fdividef(1.0f, acc.x + EPSC);

        const int px = tx * TILE + (tid & (TILE - 1));
        const int py = ty * TILE + (tid / TILE);
        float* ob = out + (size_t)b * 3 * HWP + py * WW + px;
        ob[0]       = acc.y * invd;   // R plane
        ob[HWP]     = acc.z * invd;   // G plane
        ob[2 * HWP] = acc.w * invd;   // B plane

        if (tid == 0) g_cnt[m] = 0;   // reset for next launch / graph replay
    }
}

// ---------------------------------------------------------------------------
extern "C" void kernel_launch(void* const* d_in, const int* in_sizes, int n_in,
                              void* d_out, int out_size) {
    const float* positions = (const float*)d_in[0];
    const float* colors    = (const float*)d_in[1];
    const float* opacities = (const float*)d_in[2];
    const float* scales    = (const float*)d_in[3];
    const float* qvec      = (const float*)d_in[4];
    const float* tvec      = (const float*)d_in[5];
    float* out = (float*)d_out;

    const int N = in_sizes[0] / 3;
    const int B = in_sizes[4] / 4;

    render_tiles<<<B * TILES * SPLIT, TPB>>>(out, positions, colors, opacities,
                                             scales, qvec, tvec, N);
}

// round 11
// speedup vs baseline: 1.1738x; 1.1738x over previous
#include <cuda_runtime.h>

// ---------------------------------------------------------------------------
// DifferentiableRenderer: Gaussian splat weighted-average render.
// out[b,c,y,x] = sum_n w_n*color_n / (sum_n w_n + 1e-8)
// w_n = opacity_n * exp(-0.5*((x-u_n)^2+(y-v_n)^2)/var_n)
//
// R11: revert R10 fusion (it serialized on slowest slice). Two kernels:
//   k1 render: block = (batch, 16x16 tile, gaussian slice of 8). Fused prep
//              (raw inputs -> u,v,a,bop) + conservative tile cull + stable
//              ballot/prefix compaction + per-pixel eval. Partials -> L2
//              via __stcg (consumed once by k2).
//   k2 merge:  4x more parallel than R9: 512 blocks; thread (group, pixel)
//              sums 2 slices; 64 threads/block combine 4 groups in fixed
//              order (deterministic), divide, store 3 planes.
//   Cut at w < 2^-60: per-pixel abs error <= ~7e-7 << 1e-3 budget.
// ---------------------------------------------------------------------------

#define HH 128
#define WW 128
#define HWP (HH * WW)
#define FXC 150.0f
#define FYC 150.0f
#define CXC 64.0f
#define CYC 64.0f
#define EPSC 1e-8f

#define TILE    16
#define TX_N    (WW / TILE)          // 8
#define TY_N    (HH / TILE)          // 8
#define TILES   (TX_N * TY_N)        // 64
#define SPLIT   8                    // gaussian slices per tile
#define TPB     256                  // threads per render block (1 px each)
#define CHUNK   256                  // gaussians prepped+tested per pass
#define EMIN    (-60.0f)             // log2 weight cutoff

#define MAXB    4

// per (b, tile, split, pixel) partial sums {den, r, g, b}
__device__ float4 g_part[MAXB * TILES * SPLIT * TPB];

__device__ __forceinline__ float ex2f(float x) {
    float y;
    asm("ex2.approx.ftz.f32 %0, %1;" : "=f"(y) : "f"(x));
    return y;
}
__device__ __forceinline__ float lg2f(float x) {
    float y;
    asm("lg2.approx.ftz.f32 %0, %1;" : "=f"(y) : "f"(x));
    return y;
}

// ---------------------------------------------------------------------------
// Render: blockIdx.x = ((b*TILES + tile)*SPLIT + s). 256 threads = one 16x16
// pixel tile. Scan this block's gaussian slice in chunks:
//   prep (raw inputs -> u,v,a,bop) -> tile cull -> stable compaction -> eval.
// ---------------------------------------------------------------------------
__global__ void __launch_bounds__(TPB)
render_tiles(const float* __restrict__ pos,
             const float* __restrict__ col,
             const float* __restrict__ opac,
             const float* __restrict__ scal,
             const float* __restrict__ qv,
             const float* __restrict__ tv,
             int N) {
    __shared__ float4 sga[CHUNK];      // u, v, a, bop
    __shared__ float4 sgb[CHUNK];      // cr, cg, cb, -
    __shared__ int s_wbase[TPB / 32];
    __shared__ int s_wcnt[TPB / 32];
    __shared__ int s_total;

    const int tid  = threadIdx.x;
    const int bid  = blockIdx.x;
    const int s    = bid & (SPLIT - 1);
    const int tile = (bid / SPLIT) & (TILES - 1);
    const int b    = bid / (SPLIT * TILES);

    const int tx = tile & (TX_N - 1);
    const int ty = tile / TX_N;
    const float pxf = (float)(tx * TILE + (tid & (TILE - 1)));
    const float pyf = (float)(ty * TILE + (tid / TILE));
    const float tcx = (float)(tx * TILE) + 7.5f;   // tile center
    const float tcy = (float)(ty * TILE) + 7.5f;

    // --- per-batch camera, hoisted (broadcast loads, L1 hits) ---
    float qw = qv[b * 4 + 0], qx = qv[b * 4 + 1];
    float qy = qv[b * 4 + 2], qz = qv[b * 4 + 3];
    {
        float inv = rsqrtf(qw * qw + qx * qx + qy * qy + qz * qz);
        qw *= inv; qx *= inv; qy *= inv; qz *= inv;
    }
    const float R00 = 1.0f - 2.0f * (qy * qy + qz * qz);
    const float R01 = 2.0f * (qx * qy - qz * qw);
    const float R02 = 2.0f * (qx * qz + qy * qw);
    const float R10 = 2.0f * (qx * qy + qz * qw);
    const float R11 = 1.0f - 2.0f * (qx * qx + qz * qz);
    const float R12 = 2.0f * (qy * qz - qx * qw);
    const float R20 = 2.0f * (qx * qz - qy * qw);
    const float R21 = 2.0f * (qy * qz + qx * qw);
    const float R22 = 1.0f - 2.0f * (qx * qx + qy * qy);
    const float t0 = tv[b * 3 + 0], t1 = tv[b * 3 + 1], t2 = tv[b * 3 + 2];

    const int lo = (s * N) / SPLIT;
    const int hi = ((s + 1) * N) / SPLIT;

    const int wid  = tid >> 5;
    const int lane = tid & 31;
    const unsigned lanemask_lt = (1u << lane) - 1u;

    float den = 0.f, ar = 0.f, ag = 0.f, ab = 0.f;

    for (int cb = lo; cb < hi; cb += CHUNK) {
        // --- prep + cull one gaussian per thread ---
        const int j = cb + tid;                    // gaussian index
        bool keep = false;
        float4 ga;
        if (j < hi) {
            const float px = pos[j * 3 + 0];
            const float py = pos[j * 3 + 1];
            const float pz = pos[j * 3 + 2];
            const float cxm = R00 * px + R01 * py + R02 * pz + t0;
            const float cym = R10 * px + R11 * py + R12 * pz + t1;
            const float czm = R20 * px + R21 * py + R22 * pz + t2;
            const float invz = __fdividef(1.0f, czm);
            const float u = cxm * invz * FXC + CXC;
            const float v = cym * invz * FYC + CYC;
            const float sc = scal[j];
            // a = -0.5 * log2(e) / var
            const float a = __fdividef(-0.72134752044448170f, sc * sc);
            const float bop = lg2f(opac[j]);       // opac=0 -> -inf -> culled
            ga = make_float4(u, v, a, bop);

            float dx = fmaxf(fabsf(u - tcx) - 7.5f, 0.0f);
            float dy = fmaxf(fabsf(v - tcy) - 7.5f, 0.0f);
            float mind2 = dx * dx + dy * dy;
            float emax  = fmaf(a, mind2, bop);     // a*mind2 + bop (a<0)
            keep = (emax >= EMIN);
        }

        // --- stable compaction (gaussian-index order preserved) ---
        const unsigned mask = __ballot_sync(0xffffffffu, keep);
        if (lane == 0) s_wcnt[wid] = __popc(mask);
        __syncthreads();
        if (tid == 0) {
            int acc = 0;
            #pragma unroll
            for (int w = 0; w < TPB / 32; w++) { s_wbase[w] = acc; acc += s_wcnt[w]; }
            s_total = acc;
        }
        __syncthreads();
        if (keep) {
            const int posn = s_wbase[wid] + __popc(mask & lanemask_lt);
            sga[posn] = ga;
            sgb[posn] = make_float4(col[j * 3 + 0], col[j * 3 + 1],
                                    col[j * 3 + 2], 0.0f);
        }
        __syncthreads();

        // --- evaluate survivors against this thread's pixel ---
        const int cnt = s_total;
        #pragma unroll 2
        for (int t = 0; t < cnt; t++) {
            const float4 A  = sga[t];              // u, v, a, bop (broadcast)
            const float4 Cc = sgb[t];
            const float dv = pyf - A.y;
            const float c2 = fmaf(A.z * dv, dv, A.w);
            const float du = pxf - A.x;
            const float e  = fmaf(A.z * du, du, c2);
            const float w  = ex2f(e);
            den += w;
            ar = fmaf(w, Cc.x, ar);
            ag = fmaf(w, Cc.y, ag);
            ab = fmaf(w, Cc.z, ab);
        }
        __syncthreads();
    }

    // publish partial to L2 (consumed once by merge kernel)
    __stcg(&g_part[bid * TPB + tid], make_float4(den, ar, ag, ab));
}

// ---------------------------------------------------------------------------
// Merge: grid = B*TILES*4 blocks; block = (m = b*TILES+tile, quarter q).
// Thread (g = tid>>6, p = tid&63): pixel = q*64+p, sums slices g and g+4.
// Then 64 threads combine the 4 group sums in fixed order, divide, store.
// ---------------------------------------------------------------------------
__global__ void __launch_bounds__(TPB)
merge_kernel(float* __restrict__ out) {
    __shared__ float4 sm[TPB];

    const int tid = threadIdx.x;
    const int q   = blockIdx.x & 3;          // tile quarter
    const int m   = blockIdx.x >> 2;         // b*TILES + tile
    const int tile = m & (TILES - 1);
    const int b    = m / TILES;

    const int g = tid >> 6;                  // slice group 0..3
    const int p = tid & 63;                  // pixel within quarter
    const int pix = q * 64 + p;              // pixel within tile

    // sum slices g and g+4 for this pixel (coalesced: p consecutive per warp)
    const float4 t0 = __ldcg(&g_part[(m * SPLIT + g) * TPB + pix]);
    const float4 t1 = __ldcg(&g_part[(m * SPLIT + g + 4) * TPB + pix]);
    sm[g * 64 + p] = make_float4(t0.x + t1.x, t0.y + t1.y,
                                 t0.z + t1.z, t0.w + t1.w);
    __syncthreads();

    if (tid < 64) {
        float4 acc = sm[tid];                // g = 0
        #pragma unroll
        for (int gg = 1; gg < 4; gg++) {     // fixed order -> deterministic
            const float4 t = sm[gg * 64 + tid];
            acc.x += t.x; acc.y += t.y; acc.z += t.z; acc.w += t.w;
        }
        const float invd = __fdividef(1.0f, acc.x + EPSC);

        const int mypix = q * 64 + tid;      // pixel within tile
        const int tx = tile & (TX_N - 1);
        const int ty = tile / TX_N;
        const int px = tx * TILE + (mypix & (TILE - 1));
        const int py = ty * TILE + (mypix / TILE);
        float* ob = out + (size_t)b * 3 * HWP + py * WW + px;
        ob[0]       = acc.y * invd;   // R plane
        ob[HWP]     = acc.z * invd;   // G plane
        ob[2 * HWP] = acc.w * invd;   // B plane
    }
}

// ---------------------------------------------------------------------------
extern "C" void kernel_launch(void* const* d_in, const int* in_sizes, int n_in,
                              void* d_out, int out_size) {
    const float* positions = (const float*)d_in[0];
    const float* colors    = (const float*)d_in[1];
    const float* opacities = (const float*)d_in[2];
    const float* scales    = (const float*)d_in[3];
    const float* qvec      = (const float*)d_in[4];
    const float* tvec      = (const float*)d_in[5];
    float* out = (float*)d_out;

    const int N = in_sizes[0] / 3;
    const int B = in_sizes[4] / 4;

    render_tiles<<<B * TILES * SPLIT, TPB>>>(positions, colors, opacities,
                                             scales, qvec, tvec, N);
    merge_kernel<<<B * TILES * 4, TPB>>>(out);
}